// round 3
// baseline (speedup 1.0000x reference)
#include <cuda_runtime.h>
#include <cstdint>

#define BB 64
#define RR 32
#define NN 16384
#define DD 64
#define OO 8
#define WARPS 8
#define PER_WARP (NN / WARPS)        // 2048 elements per warp
#define U4_PER_WARP (PER_WARP / 4)   // 512 uint4 per warp
#define AITERS (U4_PER_WARP / 32)    // 16 iterations per lane
#define MAXH 512                     // per-warp hit capacity (expected ~15)

// One block per b. Phase A: warp-local mask scan + ballot compaction.
// Phase B: per-lane-row rsqrt (one DRAM round trip), then L1-hot per-dim
// accumulate. Phase C: block reduce + finalize. No global scratch, no fences.
__global__ void __launch_bounds__(256) fused_kernel(
    const float* __restrict__ h_context,
    const float* __restrict__ l_local,
    const float* __restrict__ lambda_so,
    const int* __restrict__ center_o,
    const int* __restrict__ o_types,
    const unsigned int* __restrict__ adj,   // bool as 32-bit word (i32/f32 0|1)
    const unsigned int* __restrict__ two,
    float* __restrict__ out)
{
    __shared__ int   s_idx[WARPS][MAXH];
    __shared__ float s_part[WARPS][DD];
    __shared__ int   s_cnt[WARPS];
    __shared__ float sv[DD];
    __shared__ float s_scnt;

    const int b    = blockIdx.x;
    const int tid  = threadIdx.x;
    const int w    = tid >> 5;
    const int lane = tid & 31;

    const int co = center_o[b];

    // Per-warp segment pointers (warp w owns elements [w*2048, (w+1)*2048))
    const int4*  ot4 = reinterpret_cast<const int4*>(o_types + b * NN) + w * U4_PER_WARP;
    const uint4* a4  = reinterpret_cast<const uint4*>(adj     + b * NN) + w * U4_PER_WARP;
    const uint4* t4  = reinterpret_cast<const uint4*>(two     + b * NN) + w * U4_PER_WARP;

    const unsigned lt_mask = (1u << lane) - 1u;
    int cnt = 0;   // warp-uniform after each ballot round

    // ---- Phase A: vectorized scan + warp-aggregated compaction ----
    #pragma unroll 4
    for (int it = 0; it < AITERS; it++) {
        int u = it * 32 + lane;           // uint4 index within warp segment
        int4  ot = ot4[u];
        uint4 a  = a4[u];
        uint4 t  = t4[u];
        int n0 = w * PER_WARP + u * 4;    // element index within b

        bool h0 = (ot.x == co) && (a.x | t.x);
        bool h1 = (ot.y == co) && (a.y | t.y);
        bool h2 = (ot.z == co) && (a.z | t.z);
        bool h3 = (ot.w == co) && (a.w | t.w);

        unsigned m;
        m = __ballot_sync(0xffffffffu, h0);
        if (h0) { int p = cnt + __popc(m & lt_mask); if (p < MAXH) s_idx[w][p] = n0 + 0; }
        cnt += __popc(m);
        m = __ballot_sync(0xffffffffu, h1);
        if (h1) { int p = cnt + __popc(m & lt_mask); if (p < MAXH) s_idx[w][p] = n0 + 1; }
        cnt += __popc(m);
        m = __ballot_sync(0xffffffffu, h2);
        if (h2) { int p = cnt + __popc(m & lt_mask); if (p < MAXH) s_idx[w][p] = n0 + 2; }
        cnt += __popc(m);
        m = __ballot_sync(0xffffffffu, h3);
        if (h3) { int p = cnt + __popc(m & lt_mask); if (p < MAXH) s_idx[w][p] = n0 + 3; }
        cnt += __popc(m);
    }
    const int true_cnt = cnt;
    const int proc_cnt = (cnt < MAXH) ? cnt : MAXH;

    // ---- Phase B: gather + normalize + accumulate (warp-local) ----
    const float4* ctx4 = reinterpret_cast<const float4*>(h_context + (size_t)b * NN * DD);
    const float2* ctx2 = reinterpret_cast<const float2*>(h_context + (size_t)b * NN * DD);

    float accx = 0.0f, accy = 0.0f;
    for (int basei = 0; basei < proc_cnt; basei += 32) {
        // B1: lane j owns hit (basei+j): read its full 256B row, compute rsqrt.
        float r = 0.0f;
        int h = basei + lane;
        if (h < proc_cnt) {
            int n = s_idx[w][h];
            const float4* rp = ctx4 + (size_t)n * (DD / 4);
            float sq = 0.0f;
            #pragma unroll
            for (int i = 0; i < DD / 4; i++) {
                float4 v = rp[i];
                sq += v.x * v.x + v.y * v.y + v.z * v.z + v.w * v.w;
            }
            r = rsqrtf(fmaxf(sq, 1e-12f));
        }
        // B2: lane owns 2 dims; rows are L1-hot (just read on this SM).
        int lim = proc_cnt - basei; if (lim > 32) lim = 32;
        for (int j = 0; j < lim; j++) {
            float rv = __shfl_sync(0xffffffffu, r, j);
            int n = s_idx[w][basei + j];
            float2 x = ctx2[(size_t)n * (DD / 2) + lane];
            accx += x.x * rv;
            accy += x.y * rv;
        }
    }
    s_part[w][2 * lane + 0] = accx;
    s_part[w][2 * lane + 1] = accy;
    if (lane == 0) s_cnt[w] = true_cnt;
    __syncthreads();

    // ---- Phase C: block reduce + finalize ----
    if (tid < DD) {
        float s = 0.0f;
        #pragma unroll
        for (int ww = 0; ww < WARPS; ww++) s += s_part[ww][tid];
        sv[tid] = s;
    }
    if (tid == 0) {
        int s = 0;
        #pragma unroll
        for (int ww = 0; ww < WARPS; ww++) s += s_cnt[ww];
        s_scnt = (float)s;
    }
    __syncthreads();

    const float cval = s_scnt;
    #pragma unroll
    for (int rr = 0; rr < RR / WARPS; rr++) {
        int r = w + rr * WARPS;
        const float2* row = reinterpret_cast<const float2*>(
            l_local + ((size_t)b * RR + r) * DD);
        float2 x = row[lane];
        float sq = x.x * x.x + x.y * x.y;
        float dp = x.x * sv[2 * lane] + x.y * sv[2 * lane + 1];
        #pragma unroll
        for (int o = 16; o; o >>= 1) {
            sq += __shfl_xor_sync(0xffffffffu, sq, o);
            dp += __shfl_xor_sync(0xffffffffu, dp, o);
        }
        if (lane == 0) {
            float rinv = rsqrtf(fmaxf(sq, 1e-12f));
            float avg = dp * rinv / fmaxf(cval, 1e-9f);
            float lam = lambda_so[r * OO + co];
            float wv = fmaxf(lam / fmaxf(cval, 1.0f), 0.0f) * (1.0f - avg);
            out[b * RR + r] = wv;
        }
    }
}

extern "C" void kernel_launch(void* const* d_in, const int* in_sizes, int n_in,
                              void* d_out, int out_size) {
    const float*        l_local   = (const float*)d_in[0];
    const float*        h_context = (const float*)d_in[1];
    const float*        lambda_so = (const float*)d_in[2];
    const int*          center_o  = (const int*)d_in[3];
    const int*          o_types   = (const int*)d_in[4];
    const unsigned int* adj       = (const unsigned int*)d_in[5];
    const unsigned int* two       = (const unsigned int*)d_in[6];
    float*              out       = (float*)d_out;

    fused_kernel<<<BB, 256>>>(h_context, l_local, lambda_so,
                              center_o, o_types, adj, two, out);
}

// round 4
// speedup vs baseline: 1.2857x; 1.2857x over previous
#include <cuda_runtime.h>
#include <cstdint>

#define BB 64
#define RR 32
#define NN 16384
#define DD 64
#define OO 8
#define CHUNKS 16
#define NC (NN / CHUNKS)     // 1024 elements per chunk-block
#define TPB 128              // threads per accum block (4 warps)

// Per-chunk partials: plain-stored every replay, no zeroing needed.
__device__ float g_part[BB * CHUNKS * DD];
__device__ float g_pcnt[BB * CHUNKS];

// Kernel 1: one block per (b, chunk). Mask scan (int4-vectorized) ->
// smem compaction -> sparse gather+normalize -> plain-store partials.
__global__ void __launch_bounds__(TPB) accum_kernel(
    const float* __restrict__ h_context,
    const int* __restrict__ center_o,
    const int* __restrict__ o_types,
    const unsigned int* __restrict__ adj,   // bool as 32-bit word (i32/f32 0|1)
    const unsigned int* __restrict__ two)
{
    __shared__ int   s_idx[NC];
    __shared__ int   s_count;
    __shared__ float s_acc[DD];

    const int b    = blockIdx.x / CHUNKS;
    const int c    = blockIdx.x % CHUNKS;
    const int tid  = threadIdx.x;
    const int warp = tid >> 5;
    const int lane = tid & 31;

    if (tid == 0) s_count = 0;
    if (tid < DD) s_acc[tid] = 0.0f;
    __syncthreads();

    const int co = center_o[b];
    const int base = b * NN + c * NC;

    const int4*  ot4 = reinterpret_cast<const int4*>(o_types + base);
    const uint4* a4  = reinterpret_cast<const uint4*>(adj + base);
    const uint4* t4  = reinterpret_cast<const uint4*>(two + base);

    // Phase A: 256 uint4 per block over 128 threads -> 2 iters, 6 LDG.128/thread
    #pragma unroll
    for (int it = 0; it < NC / 4 / TPB; it++) {
        int i = it * TPB + tid;
        int4  ot = ot4[i];
        uint4 a  = a4[i];
        uint4 t  = t4[i];
        int n0 = c * NC + i * 4;
        if (ot.x == co && (a.x | t.x)) s_idx[atomicAdd(&s_count, 1)] = n0 + 0;
        if (ot.y == co && (a.y | t.y)) s_idx[atomicAdd(&s_count, 1)] = n0 + 1;
        if (ot.z == co && (a.z | t.z)) s_idx[atomicAdd(&s_count, 1)] = n0 + 2;
        if (ot.w == co && (a.w | t.w)) s_idx[atomicAdd(&s_count, 1)] = n0 + 3;
    }
    __syncthreads();

    const int cnt = s_count;   // expected ~7.6 per block

    // Phase B: 4 warps cooperatively process hits; lane owns 2 dims (float2).
    float accx = 0.0f, accy = 0.0f;
    const float2* ctx2 = reinterpret_cast<const float2*>(
        h_context + (size_t)b * NN * DD);
    for (int i = warp; i < cnt; i += TPB / 32) {
        int n = s_idx[i];
        float2 x = __ldg(ctx2 + (size_t)n * (DD / 2) + lane);
        float sq = x.x * x.x + x.y * x.y;
        #pragma unroll
        for (int o = 16; o; o >>= 1)
            sq += __shfl_xor_sync(0xffffffffu, sq, o);
        float rinv = rsqrtf(fmaxf(sq, 1e-12f));
        accx += x.x * rinv;
        accy += x.y * rinv;
    }
    atomicAdd(&s_acc[2 * lane + 0], accx);
    atomicAdd(&s_acc[2 * lane + 1], accy);
    __syncthreads();

    if (tid < DD) g_part[(b * CHUNKS + c) * DD + tid] = s_acc[tid];
    if (tid == 0) g_pcnt[b * CHUNKS + c] = (float)cnt;
}

// Kernel 2: one block per b, one warp per r. Reduce chunk partials (L2-hot),
// normalize l_local rows, dot, fuse lambda/relu epilogue.
__global__ void __launch_bounds__(1024) finalize_kernel(
    const float* __restrict__ l_local,
    const float* __restrict__ lambda_so,
    const int* __restrict__ center_o,
    float* __restrict__ out)
{
    const int b   = blockIdx.x;
    const int tid = threadIdx.x;

    __shared__ float sv[DD];
    __shared__ float scnt;

    if (tid < DD) {
        float s = 0.0f;
        #pragma unroll
        for (int cc = 0; cc < CHUNKS; cc++)
            s += g_part[(b * CHUNKS + cc) * DD + tid];
        sv[tid] = s;
    }
    if (tid == 0) {
        float s = 0.0f;
        #pragma unroll
        for (int cc = 0; cc < CHUNKS; cc++)
            s += g_pcnt[b * CHUNKS + cc];
        scnt = s;
    }
    __syncthreads();

    const int r    = tid >> 5;
    const int lane = tid & 31;

    const float2* row = reinterpret_cast<const float2*>(
        l_local + ((size_t)b * RR + r) * DD);
    float2 x = row[lane];

    float sq = x.x * x.x + x.y * x.y;
    float dp = x.x * sv[2 * lane] + x.y * sv[2 * lane + 1];
    #pragma unroll
    for (int o = 16; o; o >>= 1) {
        sq += __shfl_xor_sync(0xffffffffu, sq, o);
        dp += __shfl_xor_sync(0xffffffffu, dp, o);
    }

    if (lane == 0) {
        float rinv = rsqrtf(fmaxf(sq, 1e-12f));
        float cnt = scnt;
        float avg = dp * rinv / fmaxf(cnt, 1e-9f);
        int co = center_o[b];
        float lam = lambda_so[r * OO + co];
        float w = fmaxf(lam / fmaxf(cnt, 1.0f), 0.0f) * (1.0f - avg);
        out[b * RR + r] = w;
    }
}

extern "C" void kernel_launch(void* const* d_in, const int* in_sizes, int n_in,
                              void* d_out, int out_size) {
    const float*        l_local   = (const float*)d_in[0];
    const float*        h_context = (const float*)d_in[1];
    const float*        lambda_so = (const float*)d_in[2];
    const int*          center_o  = (const int*)d_in[3];
    const int*          o_types   = (const int*)d_in[4];
    const unsigned int* adj       = (const unsigned int*)d_in[5];
    const unsigned int* two       = (const unsigned int*)d_in[6];
    float*              out       = (float*)d_out;

    accum_kernel<<<BB * CHUNKS, TPB>>>(h_context, center_o, o_types, adj, two);
    finalize_kernel<<<BB, 1024>>>(l_local, lambda_so, center_o, out);
}

// round 5
// speedup vs baseline: 1.6607x; 1.2917x over previous
#include <cuda_runtime.h>
#include <cstdint>

#define BB 64
#define RR 32
#define NN 16384
#define DD 64
#define OO 8
#define CHUNKS 8
#define NC (NN / CHUNKS)   // 2048 elements per chunk-block

// Scratch: zero at the start of EVERY kernel_launch call.
// (.bss zero-init for call #1; finalize_kernel restores zeros each call.)
__device__ float g_s[BB * DD];
__device__ float g_cnt[BB];

// Kernel 1 (identical to the proven-fastest R1 accum):
// one block per (b, chunk): int4-vectorized mask scan -> smem compaction ->
// sparse gather+normalize -> global atomic accumulate.
__global__ void __launch_bounds__(256) accum_kernel(
    const float* __restrict__ h_context,
    const int* __restrict__ center_o,
    const int* __restrict__ o_types,
    const unsigned int* __restrict__ adj,   // bool as 32-bit word (i32/f32 0|1)
    const unsigned int* __restrict__ two)
{
    __shared__ int   s_idx[NC];
    __shared__ int   s_count;
    __shared__ float s_acc[DD];

    const int b    = blockIdx.x / CHUNKS;
    const int c    = blockIdx.x % CHUNKS;
    const int tid  = threadIdx.x;
    const int warp = tid >> 5;
    const int lane = tid & 31;

    if (tid == 0) s_count = 0;
    if (tid < DD) s_acc[tid] = 0.0f;
    __syncthreads();

    const int co = center_o[b];
    const int base = b * NN + c * NC;

    const int4*  ot4 = reinterpret_cast<const int4*>(o_types + base);
    const uint4* a4  = reinterpret_cast<const uint4*>(adj + base);
    const uint4* t4  = reinterpret_cast<const uint4*>(two + base);

    // Phase A: mask scan + compaction (512 int4-triples over 256 threads)
    #pragma unroll
    for (int it = 0; it < NC / 4 / 256; it++) {
        int i = it * 256 + tid;
        int4  ot = ot4[i];
        uint4 a  = a4[i];
        uint4 t  = t4[i];
        int n0 = c * NC + i * 4;
        if (ot.x == co && (a.x | t.x)) s_idx[atomicAdd(&s_count, 1)] = n0 + 0;
        if (ot.y == co && (a.y | t.y)) s_idx[atomicAdd(&s_count, 1)] = n0 + 1;
        if (ot.z == co && (a.z | t.z)) s_idx[atomicAdd(&s_count, 1)] = n0 + 2;
        if (ot.w == co && (a.w | t.w)) s_idx[atomicAdd(&s_count, 1)] = n0 + 3;
    }
    __syncthreads();

    const int cnt = s_count;   // expected ~15 per block

    // Phase B: 8 warps cooperatively process hits; lane owns 2 dims (float2).
    float accx = 0.0f, accy = 0.0f;
    const float2* ctx2 = reinterpret_cast<const float2*>(
        h_context + (size_t)b * NN * DD);
    for (int i = warp; i < cnt; i += 8) {
        int n = s_idx[i];
        float2 x = __ldg(ctx2 + (size_t)n * (DD / 2) + lane);
        float sq = x.x * x.x + x.y * x.y;
        #pragma unroll
        for (int o = 16; o; o >>= 1)
            sq += __shfl_xor_sync(0xffffffffu, sq, o);
        float rinv = rsqrtf(fmaxf(sq, 1e-12f));
        accx += x.x * rinv;
        accy += x.y * rinv;
    }
    atomicAdd(&s_acc[2 * lane + 0], accx);
    atomicAdd(&s_acc[2 * lane + 1], accy);
    __syncthreads();

    if (tid < DD) atomicAdd(&g_s[b * DD + tid], s_acc[tid]);
    if (tid == 0) atomicAdd(&g_cnt[b], (float)cnt);
}

// Kernel 2: one block per b (256 threads, 8 warps, 4 r's per warp).
// Reads g_s[b][:] (coalesced) then RESETS scratch to zero for the next
// replay (restores the launch-entry invariant; no separate zero kernel).
__global__ void __launch_bounds__(256) finalize_kernel(
    const float* __restrict__ l_local,
    const float* __restrict__ lambda_so,
    const int* __restrict__ center_o,
    float* __restrict__ out)
{
    const int b    = blockIdx.x;
    const int tid  = threadIdx.x;
    const int w    = tid >> 5;
    const int lane = tid & 31;

    __shared__ float sv[DD];
    __shared__ float scnt;

    if (tid < DD) sv[tid] = g_s[b * DD + tid];
    if (tid == 0) scnt = g_cnt[b];
    __syncthreads();

    // Self-clean scratch for next graph replay.
    if (tid < DD) g_s[b * DD + tid] = 0.0f;
    if (tid == 0) g_cnt[b] = 0.0f;

    const float cval = scnt;
    const int co = center_o[b];

    #pragma unroll
    for (int rr = 0; rr < RR / 8; rr++) {
        int r = w + rr * 8;
        const float2* row = reinterpret_cast<const float2*>(
            l_local + ((size_t)b * RR + r) * DD);
        float2 x = row[lane];
        float sq = x.x * x.x + x.y * x.y;
        float dp = x.x * sv[2 * lane] + x.y * sv[2 * lane + 1];
        #pragma unroll
        for (int o = 16; o; o >>= 1) {
            sq += __shfl_xor_sync(0xffffffffu, sq, o);
            dp += __shfl_xor_sync(0xffffffffu, dp, o);
        }
        if (lane == 0) {
            float rinv = rsqrtf(fmaxf(sq, 1e-12f));
            float avg = dp * rinv / fmaxf(cval, 1e-9f);
            float lam = lambda_so[r * OO + co];
            float wv = fmaxf(lam / fmaxf(cval, 1.0f), 0.0f) * (1.0f - avg);
            out[b * RR + r] = wv;
        }
    }
}

extern "C" void kernel_launch(void* const* d_in, const int* in_sizes, int n_in,
                              void* d_out, int out_size) {
    const float*        l_local   = (const float*)d_in[0];
    const float*        h_context = (const float*)d_in[1];
    const float*        lambda_so = (const float*)d_in[2];
    const int*          center_o  = (const int*)d_in[3];
    const int*          o_types   = (const int*)d_in[4];
    const unsigned int* adj       = (const unsigned int*)d_in[5];
    const unsigned int* two       = (const unsigned int*)d_in[6];
    float*              out       = (float*)d_out;

    accum_kernel<<<BB * CHUNKS, 256>>>(h_context, center_o, o_types, adj, two);
    finalize_kernel<<<BB, 256>>>(l_local, lambda_so, center_o, out);
}